// round 1
// baseline (speedup 1.0000x reference)
#include <cuda_runtime.h>
#include <cuda_bf16.h>
#include <mma.h>

using namespace nvcuda;

// Problem constants
#define BATCH   32768
#define D_IN    160     // 10 * 16
#define D_H1    512
#define D_H2    1024
#define D_OUT   3072

// Scratch for intermediate activations (static device arrays: allocation-free)
__device__ float g_h1[BATCH * D_H1];   // ~67 MB
__device__ float g_h2[BATCH * D_H2];   // ~134 MB

// ---------------------------------------------------------------------------
// Kernel A: capsule-norm argmax mask + FC1 (K is effectively 16) + ReLU
// One block per batch row, 128 threads.
// ---------------------------------------------------------------------------
__global__ void mask_fc1_kernel(const float* __restrict__ x,
                                const float* __restrict__ W1,
                                const float* __restrict__ b1)
{
    __shared__ float xs[D_IN];
    __shared__ float n2[10];
    __shared__ int   jm;

    const int b = blockIdx.x;
    const float* xr = x + (size_t)b * D_IN;

    for (int i = threadIdx.x; i < D_IN; i += blockDim.x) xs[i] = xr[i];
    __syncthreads();

    if (threadIdx.x < 10) {
        float s = 0.f;
        #pragma unroll
        for (int u = 0; u < 16; u++) { float v = xs[threadIdx.x * 16 + u]; s += v * v; }
        n2[threadIdx.x] = s;
    }
    __syncthreads();

    if (threadIdx.x == 0) {
        int best = 0; float bv = n2[0];
        #pragma unroll
        for (int j = 1; j < 10; j++) if (n2[j] > bv) { bv = n2[j]; best = j; }
        jm = best;
    }
    __syncthreads();

    const int base = jm * 16;
    for (int c = threadIdx.x; c < D_H1; c += blockDim.x) {
        float acc = b1[c];
        #pragma unroll
        for (int u = 0; u < 16; u++)
            acc += xs[base + u] * W1[(size_t)(base + u) * D_H1 + c];
        g_h1[(size_t)b * D_H1 + c] = fmaxf(acc, 0.f);
    }
}

// ---------------------------------------------------------------------------
// TF32 WMMA GEMM with fused bias + activation.
//   C[M,N] = act(A[M,K] @ B[K,N] + bias[N])
// Block tile 128x128, 8 warps (2 M x 4 N), warp tile 64x32 (4x2 wmma tiles).
// Fragments loaded directly from global (L1/L2-served); round-0 baseline.
// ACT: 0 = ReLU, 1 = sigmoid
// ---------------------------------------------------------------------------
template <int ACT>
__global__ __launch_bounds__(256, 2)
void gemm_bias_act(const float* __restrict__ A,
                   const float* __restrict__ Bm,
                   const float* __restrict__ bias,
                   float* __restrict__ C,
                   int M, int N, int K)
{
    const int warp = threadIdx.x >> 5;
    const int lane = threadIdx.x & 31;
    const int wm = warp & 1;          // 0..1
    const int wn = warp >> 1;         // 0..3

    const int row0 = blockIdx.y * 128 + wm * 64;
    const int col0 = blockIdx.x * 128 + wn * 32;

    wmma::fragment<wmma::accumulator, 16, 16, 8, float> acc[4][2];
    #pragma unroll
    for (int i = 0; i < 4; i++)
        #pragma unroll
        for (int j = 0; j < 2; j++)
            wmma::fill_fragment(acc[i][j], 0.f);

    wmma::fragment<wmma::matrix_a, 16, 16, 8, wmma::precision::tf32, wmma::row_major> fa[4];
    wmma::fragment<wmma::matrix_b, 16, 16, 8, wmma::precision::tf32, wmma::row_major> fb[2];

    for (int k = 0; k < K; k += 8) {
        #pragma unroll
        for (int i = 0; i < 4; i++) {
            wmma::load_matrix_sync(fa[i], A + (size_t)(row0 + 16 * i) * K + k, K);
            #pragma unroll
            for (int t = 0; t < fa[i].num_elements; t++)
                fa[i].x[t] = wmma::__float_to_tf32(fa[i].x[t]);
        }
        #pragma unroll
        for (int j = 0; j < 2; j++) {
            wmma::load_matrix_sync(fb[j], Bm + (size_t)k * N + col0 + 16 * j, N);
            #pragma unroll
            for (int t = 0; t < fb[j].num_elements; t++)
                fb[j].x[t] = wmma::__float_to_tf32(fb[j].x[t]);
        }
        #pragma unroll
        for (int i = 0; i < 4; i++)
            #pragma unroll
            for (int j = 0; j < 2; j++)
                wmma::mma_sync(acc[i][j], fa[i], fb[j], acc[i][j]);
    }

    // Epilogue: stage each 16x16 tile through smem, apply bias + activation.
    __shared__ float stage[8][16][16];
    #pragma unroll
    for (int i = 0; i < 4; i++) {
        #pragma unroll
        for (int j = 0; j < 2; j++) {
            wmma::store_matrix_sync(&stage[warp][0][0], acc[i][j], 16, wmma::mem_row_major);
            __syncwarp();
            const int r  = lane >> 1;               // 0..15
            const int c0 = (lane & 1) * 8;          // 0 or 8
            const int grow = row0 + 16 * i + r;
            #pragma unroll
            for (int t = 0; t < 8; t++) {
                const int gcol = col0 + 16 * j + c0 + t;
                float v = stage[warp][r][c0 + t] + bias[gcol];
                if (ACT == 0) {
                    v = fmaxf(v, 0.f);
                } else {
                    v = 1.f / (1.f + expf(-v));
                }
                C[(size_t)grow * N + gcol] = v;
            }
            __syncwarp();
        }
    }
}

// ---------------------------------------------------------------------------
// Launch
// ---------------------------------------------------------------------------
extern "C" void kernel_launch(void* const* d_in, const int* in_sizes, int n_in,
                              void* d_out, int out_size)
{
    const float* x  = (const float*)d_in[0];
    // d_in[1] = target (unused by forward)
    const float* W1 = (const float*)d_in[2];
    const float* b1 = (const float*)d_in[3];
    const float* W2 = (const float*)d_in[4];
    const float* b2 = (const float*)d_in[5];
    const float* W3 = (const float*)d_in[6];
    const float* b3 = (const float*)d_in[7];
    float* out = (float*)d_out;

    float* h1 = nullptr;
    float* h2 = nullptr;
    cudaGetSymbolAddress((void**)&h1, g_h1);
    cudaGetSymbolAddress((void**)&h2, g_h2);

    // Kernel A: mask + FC1 + ReLU
    mask_fc1_kernel<<<BATCH, 128>>>(x, W1, b1);

    // Kernel B: h2 = relu(h1 @ W2 + b2)   [32768,512]x[512,1024]
    {
        dim3 grid(D_H2 / 128, BATCH / 128);
        gemm_bias_act<0><<<grid, 256>>>(h1, W2, b2, h2, BATCH, D_H2, D_H1);
    }

    // Kernel C: out = sigmoid(h2 @ W3 + b3)   [32768,1024]x[1024,3072]
    {
        dim3 grid(D_OUT / 128, BATCH / 128);
        gemm_bias_act<1><<<grid, 256>>>(h2, W3, b3, out, BATCH, D_OUT, D_H2);
    }
}

// round 3
// speedup vs baseline: 2.6878x; 2.6878x over previous
#include <cuda_runtime.h>
#include <cstdint>

#define BATCH   32768
#define D_IN    160
#define D_H1    512
#define D_H2    1024
#define D_OUT   3072

// ---------------- scratch (static device arrays; allocation-free) -----------
__device__ float g_h1[BATCH * D_H1];    //  64 MB  (tf32-rounded)
__device__ float g_h2[BATCH * D_H2];    // 128 MB  (tf32-rounded)
__device__ float g_w2t[D_H2 * D_H1];    //   2 MB  W2^T [1024,512] tf32-rounded
__device__ float g_w3t[D_OUT * D_H2];   //  12 MB  W3^T [3072,1024] tf32-rounded

// ---------------- helpers ---------------------------------------------------
__device__ __forceinline__ uint32_t smem_u32(const void* p) {
    uint32_t a;
    asm("{ .reg .u64 t; cvta.to.shared.u64 t, %1; cvt.u32.u64 %0, t; }" : "=r"(a) : "l"(p));
    return a;
}
__device__ __forceinline__ float tf32_round(float v) {
    uint32_t o;
    asm("cvt.rna.tf32.f32 %0, %1;" : "=r"(o) : "f"(v));
    return __uint_as_float(o);
}
__device__ __forceinline__ void cp16(uint32_t dst, const void* src) {
    asm volatile("cp.async.cg.shared.global [%0], [%1], 16;" :: "r"(dst), "l"(src));
}
#define CP_COMMIT()  asm volatile("cp.async.commit_group;" ::: "memory")
#define CP_WAIT(n)   asm volatile("cp.async.wait_group %0;" :: "n"(n) : "memory")

__device__ __forceinline__ void mma_tf32(float* c, const uint32_t* a, const uint32_t* b) {
    asm volatile(
        "mma.sync.aligned.m16n8k8.row.col.f32.tf32.tf32.f32 "
        "{%0,%1,%2,%3}, {%4,%5,%6,%7}, {%8,%9}, {%0,%1,%2,%3};"
        : "+f"(c[0]), "+f"(c[1]), "+f"(c[2]), "+f"(c[3])
        : "r"(a[0]), "r"(a[1]), "r"(a[2]), "r"(a[3]), "r"(b[0]), "r"(b[1]));
}

// ---------------- GEMM config ----------------------------------------------
#define BM 128
#define BN 128
#define BK 16
#define STAGES 4
#define SROW 20                                   // floats per smem row (pad 4)
#define STAGE_FLOATS (BM * SROW)                  // 2560 per operand
#define STAGE_BYTES  (2 * STAGE_FLOATS * 4)       // 20480 (A + B)
#define SMEM_BIAS    0
#define SMEM_TILES   1024
#define SMEM_DYN     (SMEM_TILES + STAGES * STAGE_BYTES)   // 82944
#define GROUP_M 16                                // m-tiles per raster group

// ---------------------------------------------------------------------------
// Pipelined tf32 mma.sync GEMM:  C[M,N] = act(A[M,K] @ Bt[N,K]^T + bias)
// A row-major [M,K]; Bt row-major [N,K]; both values pre-rounded to tf32.
// ACT: 0 = relu (+tf32 round on store, feeds next GEMM), 1 = sigmoid
// ---------------------------------------------------------------------------
template <int ACT>
__global__ __launch_bounds__(256)
void gemm_mma(const float* __restrict__ A, const float* __restrict__ Bt,
              const float* __restrict__ bias, float* __restrict__ C,
              int M, int N, int K)
{
    extern __shared__ char smem[];
    float* bias_s = (float*)(smem + SMEM_BIAS);
    const uint32_t tiles_u32 = smem_u32(smem + SMEM_TILES);

    const int tid  = threadIdx.x;
    const int wid  = tid >> 5, lane = tid & 31;
    const int g    = lane >> 2, tg = lane & 3;
    const int wm   = wid & 3, wn = wid >> 2;       // 4 x 2 warp grid

    // grouped rasterization: GROUP_M m-tiles x all n-tiles per group
    const int num_n = N / BN;
    const int pid   = blockIdx.x;
    const int tpg   = GROUP_M * num_n;
    const int grp   = pid / tpg;
    const int rem   = pid % tpg;
    const int mt    = grp * GROUP_M + rem % GROUP_M;
    const int ntile = rem / GROUP_M;
    const int m0 = mt * BM, n0 = ntile * BN;

    for (int i = tid; i < BN; i += 256) bias_s[i] = bias[n0 + i];

    const int KT = K / BK;

    // -------- stage loader: 2 A + 2 B cp.async(16B) per thread -------------
    auto load_stage = [&](int s, int kt) {
        const uint32_t base = tiles_u32 + s * STAGE_BYTES;
        #pragma unroll
        for (int j = 0; j < 2; j++) {
            int q   = tid + j * 256;               // 0..511
            int row = q >> 2, cg = q & 3;
            cp16(base + row * (SROW * 4) + cg * 16,
                 A + (size_t)(m0 + row) * K + kt * BK + cg * 4);
            cp16(base + (STAGE_FLOATS * 4) + row * (SROW * 4) + cg * 16,
                 Bt + (size_t)(n0 + row) * K + kt * BK + cg * 4);
        }
    };

    #pragma unroll
    for (int s = 0; s < STAGES - 1; s++) { load_stage(s, s); CP_COMMIT(); }

    float acc[2][8][4];
    #pragma unroll
    for (int im = 0; im < 2; im++)
        #pragma unroll
        for (int in = 0; in < 8; in++)
            #pragma unroll
            for (int q = 0; q < 4; q++) acc[im][in][q] = 0.f;

    const float* smf = (const float*)(smem + SMEM_TILES);

    for (int kt = 0; kt < KT; kt++) {
        CP_WAIT(STAGES - 2);
        __syncthreads();

        int kn = kt + STAGES - 1;
        if (kn < KT) load_stage(kn % STAGES, kn);
        CP_COMMIT();

        const int s = kt % STAGES;
        const float* As = smf + s * (STAGE_BYTES / 4);
        const float* Bs = As + STAGE_FLOATS;

        #pragma unroll
        for (int ks = 0; ks < 2; ks++) {
            const int kk = ks * 8;
            uint32_t af[2][4], bf[8][2];
            #pragma unroll
            for (int im = 0; im < 2; im++) {
                const int r = wm * 32 + im * 16 + g;
                af[im][0] = __float_as_uint(As[(r)     * SROW + kk + tg]);
                af[im][1] = __float_as_uint(As[(r + 8) * SROW + kk + tg]);
                af[im][2] = __float_as_uint(As[(r)     * SROW + kk + tg + 4]);
                af[im][3] = __float_as_uint(As[(r + 8) * SROW + kk + tg + 4]);
            }
            #pragma unroll
            for (int in = 0; in < 8; in++) {
                const int c = wn * 64 + in * 8 + g;
                bf[in][0] = __float_as_uint(Bs[c * SROW + kk + tg]);
                bf[in][1] = __float_as_uint(Bs[c * SROW + kk + tg + 4]);
            }
            #pragma unroll
            for (int im = 0; im < 2; im++)
                #pragma unroll
                for (int in = 0; in < 8; in++)
                    mma_tf32(acc[im][in], af[im], bf[in]);
        }
        __syncthreads();
    }

    // -------- epilogue: bias + act, direct float2 stores --------------------
    #pragma unroll
    for (int im = 0; im < 2; im++) {
        #pragma unroll
        for (int in = 0; in < 8; in++) {
            const int lrow = wm * 32 + im * 16 + g;
            const int lcol = wn * 64 + in * 8 + 2 * tg;
            #pragma unroll
            for (int h = 0; h < 2; h++) {                 // rows g, g+8
                float v0 = acc[im][in][2 * h]     + bias_s[lcol];
                float v1 = acc[im][in][2 * h + 1] + bias_s[lcol + 1];
                if (ACT == 0) {
                    v0 = tf32_round(fmaxf(v0, 0.f));
                    v1 = tf32_round(fmaxf(v1, 0.f));
                } else {
                    v0 = 1.f / (1.f + __expf(-v0));
                    v1 = 1.f / (1.f + __expf(-v1));
                }
                *(float2*)(C + (size_t)(m0 + lrow + 8 * h) * N + n0 + lcol) =
                    make_float2(v0, v1);
            }
        }
    }
}

// ---------------------------------------------------------------------------
// Kernel A: capsule argmax mask + FC1 (effective K=16) + ReLU, tf32-rounded.
// ---------------------------------------------------------------------------
__global__ void mask_fc1_kernel(const float* __restrict__ x,
                                const float* __restrict__ W1,
                                const float* __restrict__ b1)
{
    __shared__ float xs[D_IN];
    __shared__ float n2[10];
    __shared__ int   jm;

    const int b = blockIdx.x;
    const float* xr = x + (size_t)b * D_IN;

    for (int i = threadIdx.x; i < D_IN; i += blockDim.x) xs[i] = xr[i];
    __syncthreads();

    if (threadIdx.x < 10) {
        float s = 0.f;
        #pragma unroll
        for (int u = 0; u < 16; u++) { float v = xs[threadIdx.x * 16 + u]; s += v * v; }
        n2[threadIdx.x] = s;
    }
    __syncthreads();
    if (threadIdx.x == 0) {
        int best = 0; float bv = n2[0];
        #pragma unroll
        for (int j = 1; j < 10; j++) if (n2[j] > bv) { bv = n2[j]; best = j; }
        jm = best;
    }
    __syncthreads();

    const int base = jm * 16;
    for (int c = threadIdx.x; c < D_H1; c += blockDim.x) {
        float acc = b1[c];
        #pragma unroll
        for (int u = 0; u < 16; u++)
            acc += xs[base + u] * W1[(size_t)(base + u) * D_H1 + c];
        g_h1[(size_t)b * D_H1 + c] = tf32_round(fmaxf(acc, 0.f));
    }
}

// ---------------------------------------------------------------------------
// Transpose + tf32-round:  W [K,N] row-major  ->  Wt [N,K] row-major
// grid (N/32, K/32), block (32, 8)
// ---------------------------------------------------------------------------
__global__ void transpose_kernel(const float* __restrict__ W, float* __restrict__ Wt,
                                 int K, int N)
{
    __shared__ float t[32][33];
    const int k0 = blockIdx.y * 32, n0 = blockIdx.x * 32;
    #pragma unroll
    for (int j = 0; j < 4; j++) {
        int k = threadIdx.y + j * 8;
        t[k][threadIdx.x] = W[(size_t)(k0 + k) * N + n0 + threadIdx.x];
    }
    __syncthreads();
    #pragma unroll
    for (int j = 0; j < 4; j++) {
        int n = threadIdx.y + j * 8;
        Wt[(size_t)(n0 + n) * K + k0 + threadIdx.x] = tf32_round(t[threadIdx.x][n]);
    }
}

// ---------------------------------------------------------------------------
extern "C" void kernel_launch(void* const* d_in, const int* in_sizes, int n_in,
                              void* d_out, int out_size)
{
    const float* x  = (const float*)d_in[0];
    const float* W1 = (const float*)d_in[2];
    const float* b1 = (const float*)d_in[3];
    const float* W2 = (const float*)d_in[4];
    const float* b2 = (const float*)d_in[5];
    const float* W3 = (const float*)d_in[6];
    const float* b3 = (const float*)d_in[7];
    float* out = (float*)d_out;

    float *h1, *h2, *w2t, *w3t;
    cudaGetSymbolAddress((void**)&h1,  g_h1);
    cudaGetSymbolAddress((void**)&h2,  g_h2);
    cudaGetSymbolAddress((void**)&w2t, g_w2t);
    cudaGetSymbolAddress((void**)&w3t, g_w3t);

    cudaFuncSetAttribute(gemm_mma<0>, cudaFuncAttributeMaxDynamicSharedMemorySize, SMEM_DYN);
    cudaFuncSetAttribute(gemm_mma<1>, cudaFuncAttributeMaxDynamicSharedMemorySize, SMEM_DYN);

    // weight transposes (tiny)
    transpose_kernel<<<dim3(D_H2 / 32, D_H1 / 32), dim3(32, 8)>>>(W2, w2t, D_H1, D_H2);
    transpose_kernel<<<dim3(D_OUT / 32, D_H2 / 32), dim3(32, 8)>>>(W3, w3t, D_H2, D_OUT);

    // mask + FC1 + ReLU
    mask_fc1_kernel<<<BATCH, 128>>>(x, W1, b1);

    // h2 = relu(h1 @ W2 + b2)
    gemm_mma<0><<<(BATCH / BM) * (D_H2 / BN), 256, SMEM_DYN>>>(
        h1, w2t, b2, h2, BATCH, D_H2, D_H1);

    // out = sigmoid(h2 @ W3 + b3)
    gemm_mma<1><<<(BATCH / BM) * (D_OUT / BN), 256, SMEM_DYN>>>(
        h2, w3t, b3, out, BATCH, D_OUT, D_H2);
}